// round 1
// baseline (speedup 1.0000x reference)
#include <cuda_runtime.h>
#include <cuda_bf16.h>

#define S_LEN 4096
#define DIM   1280
#define NH    16
#define HD    80
#define SEG   512

// Scratch (no allocations allowed -> __device__ globals)
__device__ float g_qkv [S_LEN * 3 * DIM];   // [S, 3840]
__device__ float g_q   [NH * S_LEN * HD];   // [H, S, D] (roped)
__device__ float g_k   [NH * S_LEN * HD];   // [H, S, D] (roped)
__device__ float g_v   [NH * S_LEN * HD];   // [H, S, D]
__device__ float g_attn[S_LEN * DIM];       // [S, 1280]

// ---------------------------------------------------------------------------
// GEMM: C[M,N] = A[M,K] @ B[N,K]^T + bias[N]   (both operands K-major)
// 128x128 tile, BK=16, 256 threads, 8x8 per-thread micro-tile.
// ---------------------------------------------------------------------------
template<int BM, int BN, int BK>
__global__ void __launch_bounds__(256)
gemm_tn_bias(const float* __restrict__ A, const float* __restrict__ B,
             const float* __restrict__ bias, float* __restrict__ C,
             int M, int N, int K)
{
    __shared__ float As[BK][BM + 4];
    __shared__ float Bs[BK][BN + 4];

    const int tid = threadIdx.x;
    const int bm  = blockIdx.y * BM;
    const int bn  = blockIdx.x * BN;
    const int tm  = tid & 15;   // 0..15
    const int tn  = tid >> 4;   // 0..15

    float acc[8][8];
#pragma unroll
    for (int i = 0; i < 8; ++i)
#pragma unroll
        for (int j = 0; j < 8; ++j) acc[i][j] = 0.f;

    for (int k0 = 0; k0 < K; k0 += BK) {
        // Load A tile: 128 rows x 16 k  (2048 elems / 256 thr = 8 each)
#pragma unroll
        for (int i = 0; i < (BM * BK) / 256; ++i) {
            int l   = i * 256 + tid;
            int row = l >> 4;
            int kk  = l & 15;
            As[kk][row] = A[(size_t)(bm + row) * K + k0 + kk];
        }
#pragma unroll
        for (int i = 0; i < (BN * BK) / 256; ++i) {
            int l   = i * 256 + tid;
            int row = l >> 4;
            int kk  = l & 15;
            Bs[kk][row] = B[(size_t)(bn + row) * K + k0 + kk];
        }
        __syncthreads();

#pragma unroll
        for (int kk = 0; kk < BK; ++kk) {
            float4 a0 = *(const float4*)&As[kk][tm * 8];
            float4 a1 = *(const float4*)&As[kk][tm * 8 + 4];
            float4 b0 = *(const float4*)&Bs[kk][tn * 8];
            float4 b1 = *(const float4*)&Bs[kk][tn * 8 + 4];
            float a[8] = {a0.x, a0.y, a0.z, a0.w, a1.x, a1.y, a1.z, a1.w};
            float b[8] = {b0.x, b0.y, b0.z, b0.w, b1.x, b1.y, b1.z, b1.w};
#pragma unroll
            for (int i = 0; i < 8; ++i)
#pragma unroll
                for (int j = 0; j < 8; ++j)
                    acc[i][j] += a[i] * b[j];
        }
        __syncthreads();
    }

    // Epilogue with bias
    float bb[8];
#pragma unroll
    for (int j = 0; j < 8; ++j) bb[j] = bias[bn + tn * 8 + j];
#pragma unroll
    for (int i = 0; i < 8; ++i) {
        int r = bm + tm * 8 + i;
        float4* crow = (float4*)&C[(size_t)r * N + bn + tn * 8];
        float4 c0, c1;
        c0.x = acc[i][0] + bb[0]; c0.y = acc[i][1] + bb[1];
        c0.z = acc[i][2] + bb[2]; c0.w = acc[i][3] + bb[3];
        c1.x = acc[i][4] + bb[4]; c1.y = acc[i][5] + bb[5];
        c1.z = acc[i][6] + bb[6]; c1.w = acc[i][7] + bb[7];
        crow[0] = c0; crow[1] = c1;
    }
}

// ---------------------------------------------------------------------------
// RoPE + split qkv[S,3840] -> g_q/g_k (roped) / g_v, layout [H, S, D]
// ---------------------------------------------------------------------------
__global__ void rope_split(const float* __restrict__ cosb,
                           const float* __restrict__ sinb)
{
    int idx = blockIdx.x * blockDim.x + threadIdx.x;
    if (idx >= S_LEN * NH * HD) return;
    int d = idx % HD;
    int h = (idx / HD) % NH;
    int s = idx / (HD * NH);

    const float* row = g_qkv + (size_t)s * 3 * DIM;
    float c  = cosb[s * HD + d];
    float sn = sinb[s * HD + d];
    int base = h * HD;

    float qv = row[base + d];
    float qr = (d < HD / 2) ? -row[base + d + HD / 2] : row[base + d - HD / 2];
    float kv = row[DIM + base + d];
    float kr = (d < HD / 2) ? -row[DIM + base + d + HD / 2]
                            :  row[DIM + base + d - HD / 2];

    int o = (h * S_LEN + s) * HD + d;
    g_q[o] = qv * c + qr * sn;
    g_k[o] = kv * c + kr * sn;
    g_v[o] = row[2 * DIM + base + d];
}

// ---------------------------------------------------------------------------
// Attention: per block = (head, segment, 64-row q tile). Online softmax over
// 8 chunks of 64 keys. Segments are uniform 512 => block-diagonal mask is
// implicit (tiles never cross a segment boundary).
// ---------------------------------------------------------------------------
#define QS_STRIDE 81
#define KS_STRIDE 81
#define VS_STRIDE 80
#define SC_STRIDE 65
#define ATTN_SMEM ((64*QS_STRIDE + 64*KS_STRIDE + 64*VS_STRIDE + 64*SC_STRIDE + 3*64) * 4)

__global__ void __launch_bounds__(256) attn_kernel()
{
    extern __shared__ float sm[];
    float* Qs = sm;                       // [64][81]
    float* Ks = Qs + 64 * QS_STRIDE;      // [64][81]
    float* Vs = Ks + 64 * KS_STRIDE;      // [64][80]
    float* Sc = Vs + 64 * VS_STRIDE;      // [64][65]
    float* rm = Sc + 64 * SC_STRIDE;      // [64]
    float* rl = rm + 64;                  // [64]
    float* rc = rl + 64;                  // [64]

    const int qt  = blockIdx.x & 7;
    const int sg  = (blockIdx.x >> 3) & 7;
    const int h   = blockIdx.x >> 6;
    const int tid = threadIdx.x;
    const int s0  = sg * SEG + qt * 64;

    const float scale = 0.11180339887498948f;  // 1/sqrt(80)

    // Load Q tile
    const float* Qg = g_q + (size_t)(h * S_LEN + s0) * HD;
    for (int l = tid; l < 64 * HD; l += 256) {
        int r = l / HD, d = l % HD;
        Qs[r * QS_STRIDE + d] = Qg[r * HD + d];
    }
    if (tid < 64) { rm[tid] = -1e30f; rl[tid] = 0.f; }

    const int row = tid >> 2;          // 0..63
    const int d0  = (tid & 3) * 20;    // 0,20,40,60
    float o[20];
#pragma unroll
    for (int i = 0; i < 20; ++i) o[i] = 0.f;
    __syncthreads();

    for (int kc = 0; kc < SEG / 64; ++kc) {
        const float* Kg = g_k + (size_t)(h * S_LEN + sg * SEG + kc * 64) * HD;
        const float* Vg = g_v + (size_t)(h * S_LEN + sg * SEG + kc * 64) * HD;
        for (int l = tid; l < 64 * HD; l += 256) {
            int r = l / HD, d = l % HD;
            Ks[r * KS_STRIDE + d] = Kg[r * HD + d];
            Vs[r * VS_STRIDE + d] = Vg[r * HD + d];
        }
        __syncthreads();

        // Scores: 64x64, each thread a 4x4 micro-tile
        {
            const int ti = (tid & 15) << 2;
            const int tj = (tid >> 4) << 2;
            float acc[4][4];
#pragma unroll
            for (int a = 0; a < 4; ++a)
#pragma unroll
                for (int b = 0; b < 4; ++b) acc[a][b] = 0.f;
#pragma unroll 8
            for (int k = 0; k < HD; ++k) {
                float qv[4], kv[4];
#pragma unroll
                for (int a = 0; a < 4; ++a) qv[a] = Qs[(ti + a) * QS_STRIDE + k];
#pragma unroll
                for (int b = 0; b < 4; ++b) kv[b] = Ks[(tj + b) * KS_STRIDE + k];
#pragma unroll
                for (int a = 0; a < 4; ++a)
#pragma unroll
                    for (int b = 0; b < 4; ++b)
                        acc[a][b] += qv[a] * kv[b];
            }
#pragma unroll
            for (int a = 0; a < 4; ++a)
#pragma unroll
                for (int b = 0; b < 4; ++b)
                    Sc[(ti + a) * SC_STRIDE + tj + b] = acc[a][b] * scale;
        }
        __syncthreads();

        // Online softmax update (one thread per row)
        if (tid < 64) {
            float mold = rm[tid];
            float mx = mold;
            float* srow = Sc + tid * SC_STRIDE;
#pragma unroll 8
            for (int j = 0; j < 64; ++j) mx = fmaxf(mx, srow[j]);
            float c  = __expf(mold - mx);
            float ls = 0.f;
#pragma unroll 8
            for (int j = 0; j < 64; ++j) {
                float p = __expf(srow[j] - mx);
                srow[j] = p;
                ls += p;
            }
            rl[tid] = rl[tid] * c + ls;
            rm[tid] = mx;
            rc[tid] = c;
        }
        __syncthreads();

        // O = O*c + P @ V  (4 threads per row, 20 dims each)
        {
            float c = rc[row];
#pragma unroll
            for (int i = 0; i < 20; ++i) o[i] *= c;
            const float* srow = Sc + row * SC_STRIDE;
#pragma unroll 4
            for (int j = 0; j < 64; ++j) {
                float p = srow[j];
                const float4* v4 = (const float4*)&Vs[j * VS_STRIDE + d0];
#pragma unroll
                for (int q = 0; q < 5; ++q) {
                    float4 v = v4[q];
                    o[q * 4 + 0] += p * v.x;
                    o[q * 4 + 1] += p * v.y;
                    o[q * 4 + 2] += p * v.z;
                    o[q * 4 + 3] += p * v.w;
                }
            }
        }
        __syncthreads();
    }

    // Normalize + write [S, DIM]
    float inv = 1.f / rl[row];
    float* og = g_attn + (size_t)(s0 + row) * DIM + h * HD + d0;
#pragma unroll
    for (int i = 0; i < 20; ++i) og[i] = o[i] * inv;
}

// ---------------------------------------------------------------------------
extern "C" void kernel_launch(void* const* d_in, const int* in_sizes, int n_in,
                              void* d_out, int out_size)
{
    const float* hs     = (const float*)d_in[0];
    const float* cosb   = (const float*)d_in[1];
    const float* sinb   = (const float*)d_in[2];
    const float* qkv_w  = (const float*)d_in[3];
    const float* qkv_b  = (const float*)d_in[4];
    const float* proj_w = (const float*)d_in[5];
    const float* proj_b = (const float*)d_in[6];
    float* out = (float*)d_out;

    float *qkv_ptr, *attn_ptr;
    cudaGetSymbolAddress((void**)&qkv_ptr,  g_qkv);
    cudaGetSymbolAddress((void**)&attn_ptr, g_attn);

    cudaFuncSetAttribute(attn_kernel,
                         cudaFuncAttributeMaxDynamicSharedMemorySize, ATTN_SMEM);

    // 1) QKV GEMM: [4096,3840] = hs @ qkv_w^T + b
    {
        dim3 grid(3 * DIM / 128, S_LEN / 128);
        gemm_tn_bias<128, 128, 16><<<grid, 256>>>(hs, qkv_w, qkv_b, qkv_ptr,
                                                  S_LEN, 3 * DIM, DIM);
    }
    // 2) RoPE + split into [H,S,D]
    {
        int total = S_LEN * NH * HD;
        rope_split<<<(total + 255) / 256, 256>>>(cosb, sinb);
    }
    // 3) Block-diagonal attention
    attn_kernel<<<NH * (S_LEN / SEG) * (SEG / 64), 256, ATTN_SMEM>>>();
    // 4) Proj GEMM: out = attn @ proj_w^T + b
    {
        dim3 grid(DIM / 128, S_LEN / 128);
        gemm_tn_bias<128, 128, 16><<<grid, 256>>>(attn_ptr, proj_w, proj_b, out,
                                                  S_LEN, DIM, DIM);
    }
}

// round 3
// speedup vs baseline: 1.9533x; 1.9533x over previous
#include <cuda_runtime.h>
#include <cuda_bf16.h>
#include <cstdint>

#define S_LEN 4096
#define DIM   1280
#define NH    16
#define HD    80
#define SEG   512

// Scratch (no allocations allowed -> __device__ globals)
__device__ float g_qkv [S_LEN * 3 * DIM];   // [S, 3840]
__device__ float g_q   [NH * S_LEN * HD];   // [H, S, D] (roped)
__device__ float g_k   [NH * S_LEN * HD];   // [H, S, D] (roped)
__device__ float g_v   [NH * S_LEN * HD];   // [H, S, D]
__device__ float g_attn[S_LEN * DIM];       // [S, 1280]

// ===========================================================================
// mma.sync bf16 GEMM with 3-pass split precision (bf16x3)
//   C[M,N] = A[M,K] @ B[N,K]^T + bias[N], fp32 in/out, ~fp32 accuracy.
// CTA tile 128x128, BK=16, 256 threads = 8 warps (4M x 2N), warp tile 32x64.
// Fragments loaded with ldmatrix.x4 from 48B-stride smem rows (conflict-free).
// ===========================================================================

#define ROWB 48                    // bytes per smem row: 16 bf16 (32B) + 16B pad
#define TILE_B (128 * ROWB)        // 6144 B per tile
// stage = [Ah][Al][Bh][Bl], double buffered
#define GSMEM_TOTAL (2 * 4 * TILE_B)   // 49152 B

#define LDSM4(r0, r1, r2, r3, addr) \
    asm volatile("ldmatrix.sync.aligned.m8n8.x4.shared.b16 {%0,%1,%2,%3}, [%4];" \
        : "=r"(r0), "=r"(r1), "=r"(r2), "=r"(r3) : "r"(addr))

#define MMA16816(d, a0, a1, a2, a3, b0, b1) \
    asm volatile("mma.sync.aligned.m16n8k16.row.col.f32.bf16.bf16.f32 " \
        "{%0,%1,%2,%3}, {%4,%5,%6,%7}, {%8,%9}, {%0,%1,%2,%3};" \
        : "+f"((d)[0]), "+f"((d)[1]), "+f"((d)[2]), "+f"((d)[3]) \
        : "r"(a0), "r"(a1), "r"(a2), "r"(a3), "r"(b0), "r"(b1))

__device__ __forceinline__ uint32_t smem_u32(const void* p) {
    uint32_t a;
    asm("{ .reg .u64 t; cvta.to.shared.u64 t, %1; cvt.u32.u64 %0, t; }"
        : "=r"(a) : "l"(p));
    return a;
}

// split a float4 into hi/lo bf16 quads and store 8B each
__device__ __forceinline__ void store_hl(char* hp, char* lp, float4 v) {
    __nv_bfloat16 h0 = __float2bfloat16(v.x);
    __nv_bfloat16 h1 = __float2bfloat16(v.y);
    __nv_bfloat16 h2 = __float2bfloat16(v.z);
    __nv_bfloat16 h3 = __float2bfloat16(v.w);
    __nv_bfloat16 l0 = __float2bfloat16(v.x - __bfloat162float(h0));
    __nv_bfloat16 l1 = __float2bfloat16(v.y - __bfloat162float(h1));
    __nv_bfloat16 l2 = __float2bfloat16(v.z - __bfloat162float(h2));
    __nv_bfloat16 l3 = __float2bfloat16(v.w - __bfloat162float(h3));
    __nv_bfloat162 hp0(h0, h1), hp1(h2, h3), lp0(l0, l1), lp1(l2, l3);
    uint2 hv, lv;
    hv.x = *(uint32_t*)&hp0; hv.y = *(uint32_t*)&hp1;
    lv.x = *(uint32_t*)&lp0; lv.y = *(uint32_t*)&lp1;
    *(uint2*)hp = hv;
    *(uint2*)lp = lv;
}

__global__ void __launch_bounds__(256)
gemm_bf16x3(const float* __restrict__ A, const float* __restrict__ B,
            const float* __restrict__ bias, float* __restrict__ C,
            int M, int N, int K)
{
    extern __shared__ char gsm[];
    const uint32_t sb = smem_u32(gsm);

    const int tid = threadIdx.x;
    const int wid = tid >> 5;
    const int L   = tid & 31;
    const int bm  = blockIdx.y * 128;
    const int bn  = blockIdx.x * 128;
    const int wm  = (wid & 3) * 32;   // warp M offset
    const int wn  = (wid >> 2) * 64;  // warp N offset

    // staging indices: 2 float4 per operand per thread
    const int r0g = (tid) >> 2,        q0 = (tid & 3);
    const int r1g = (256 + tid) >> 2,  q1 = (tid & 3);   // r1g = 64 + r0g

    // ldmatrix within-tile byte offsets (h tiles; l = +TILE_B)
    uint32_t a_off[2], b_off[4];
#pragma unroll
    for (int mt = 0; mt < 2; ++mt)
        a_off[mt] = (uint32_t)((wm + mt * 16 + (L & 7) + ((L >> 3) & 1) * 8) * ROWB
                               + (L >> 4) * 16);
#pragma unroll
    for (int np = 0; np < 4; ++np)
        b_off[np] = (uint32_t)((wn + np * 16 + (L & 7) + (L >> 4) * 8) * ROWB
                               + ((L >> 3) & 1) * 16);

    float acc[2][8][4];
#pragma unroll
    for (int mt = 0; mt < 2; ++mt)
#pragma unroll
        for (int nt = 0; nt < 8; ++nt)
#pragma unroll
            for (int i = 0; i < 4; ++i) acc[mt][nt][i] = 0.f;

    const int nstg = K / 16;

    // prologue: load stage 0
    float4 ra0 = *(const float4*)(A + (size_t)(bm + r0g) * K + q0 * 4);
    float4 ra1 = *(const float4*)(A + (size_t)(bm + r1g) * K + q1 * 4);
    float4 rb0 = *(const float4*)(B + (size_t)(bn + r0g) * K + q0 * 4);
    float4 rb1 = *(const float4*)(B + (size_t)(bn + r1g) * K + q1 * 4);

    for (int s = 0; s < nstg; ++s) {
        char* st = gsm + (s & 1) * (4 * TILE_B);
        // store hi/lo tiles
        store_hl(st + 0 * TILE_B + r0g * ROWB + q0 * 8,
                 st + 1 * TILE_B + r0g * ROWB + q0 * 8, ra0);
        store_hl(st + 0 * TILE_B + r1g * ROWB + q1 * 8,
                 st + 1 * TILE_B + r1g * ROWB + q1 * 8, ra1);
        store_hl(st + 2 * TILE_B + r0g * ROWB + q0 * 8,
                 st + 3 * TILE_B + r0g * ROWB + q0 * 8, rb0);
        store_hl(st + 2 * TILE_B + r1g * ROWB + q1 * 8,
                 st + 3 * TILE_B + r1g * ROWB + q1 * 8, rb1);

        // prefetch next stage into registers
        if (s + 1 < nstg) {
            int k0 = (s + 1) * 16;
            ra0 = *(const float4*)(A + (size_t)(bm + r0g) * K + k0 + q0 * 4);
            ra1 = *(const float4*)(A + (size_t)(bm + r1g) * K + k0 + q1 * 4);
            rb0 = *(const float4*)(B + (size_t)(bn + r0g) * K + k0 + q0 * 4);
            rb1 = *(const float4*)(B + (size_t)(bn + r1g) * K + k0 + q1 * 4);
        }
        __syncthreads();

        const uint32_t base = sb + (uint32_t)((s & 1) * (4 * TILE_B));

        uint32_t ah[2][4], al[2][4], bh[4][4], bl[4][4];
#pragma unroll
        for (int mt = 0; mt < 2; ++mt) {
            LDSM4(ah[mt][0], ah[mt][1], ah[mt][2], ah[mt][3],
                  base + 0 * TILE_B + a_off[mt]);
            LDSM4(al[mt][0], al[mt][1], al[mt][2], al[mt][3],
                  base + 1 * TILE_B + a_off[mt]);
        }
#pragma unroll
        for (int np = 0; np < 4; ++np) {
            LDSM4(bh[np][0], bh[np][1], bh[np][2], bh[np][3],
                  base + 2 * TILE_B + b_off[np]);
            LDSM4(bl[np][0], bl[np][1], bl[np][2], bl[np][3],
                  base + 3 * TILE_B + b_off[np]);
        }

#pragma unroll
        for (int mt = 0; mt < 2; ++mt)
#pragma unroll
            for (int np = 0; np < 4; ++np)
#pragma unroll
                for (int hf = 0; hf < 2; ++hf) {
                    const int nt = np * 2 + hf;
                    // hh
                    MMA16816(acc[mt][nt], ah[mt][0], ah[mt][1], ah[mt][2], ah[mt][3],
                             bh[np][hf * 2], bh[np][hf * 2 + 1]);
                    // hl
                    MMA16816(acc[mt][nt], ah[mt][0], ah[mt][1], ah[mt][2], ah[mt][3],
                             bl[np][hf * 2], bl[np][hf * 2 + 1]);
                    // lh
                    MMA16816(acc[mt][nt], al[mt][0], al[mt][1], al[mt][2], al[mt][3],
                             bh[np][hf * 2], bh[np][hf * 2 + 1]);
                }
        // one sync per iter is sufficient (double buffer; see analysis)
    }

    // Epilogue: c0,c1 -> (row, col..col+1); c2,c3 -> (row+8)
#pragma unroll
    for (int mt = 0; mt < 2; ++mt) {
        const int row = bm + wm + mt * 16 + (L >> 2);
#pragma unroll
        for (int nt = 0; nt < 8; ++nt) {
            const int col = bn + wn + nt * 8 + (L & 3) * 2;
            float2 bv = *(const float2*)(bias + col);
            float2 o0, o1;
            o0.x = acc[mt][nt][0] + bv.x; o0.y = acc[mt][nt][1] + bv.y;
            o1.x = acc[mt][nt][2] + bv.x; o1.y = acc[mt][nt][3] + bv.y;
            *(float2*)(C + (size_t)row * N + col)       = o0;
            *(float2*)(C + (size_t)(row + 8) * N + col) = o1;
        }
    }
}

// ---------------------------------------------------------------------------
// RoPE + split qkv[S,3840] -> g_q/g_k (roped) / g_v, layout [H, S, D]
// ---------------------------------------------------------------------------
__global__ void rope_split(const float* __restrict__ cosb,
                           const float* __restrict__ sinb)
{
    int idx = blockIdx.x * blockDim.x + threadIdx.x;
    if (idx >= S_LEN * NH * HD) return;
    int d = idx % HD;
    int h = (idx / HD) % NH;
    int s = idx / (HD * NH);

    const float* row = g_qkv + (size_t)s * 3 * DIM;
    float c  = cosb[s * HD + d];
    float sn = sinb[s * HD + d];
    int base = h * HD;

    float qv = row[base + d];
    float qr = (d < HD / 2) ? -row[base + d + HD / 2] : row[base + d - HD / 2];
    float kv = row[DIM + base + d];
    float kr = (d < HD / 2) ? -row[DIM + base + d + HD / 2]
                            :  row[DIM + base + d - HD / 2];

    int o = (h * S_LEN + s) * HD + d;
    g_q[o] = qv * c + qr * sn;
    g_k[o] = kv * c + kr * sn;
    g_v[o] = row[2 * DIM + base + d];
}

// ---------------------------------------------------------------------------
// Attention (unchanged — known correct)
// ---------------------------------------------------------------------------
#define QS_STRIDE 81
#define KS_STRIDE 81
#define VS_STRIDE 80
#define SC_STRIDE 65
#define ATTN_SMEM ((64*QS_STRIDE + 64*KS_STRIDE + 64*VS_STRIDE + 64*SC_STRIDE + 3*64) * 4)

__global__ void __launch_bounds__(256) attn_kernel()
{
    extern __shared__ float sm[];
    float* Qs = sm;                       // [64][81]
    float* Ks = Qs + 64 * QS_STRIDE;      // [64][81]
    float* Vs = Ks + 64 * KS_STRIDE;      // [64][80]
    float* Sc = Vs + 64 * VS_STRIDE;      // [64][65]
    float* rm = Sc + 64 * SC_STRIDE;      // [64]
    float* rl = rm + 64;                  // [64]
    float* rc = rl + 64;                  // [64]

    const int qt  = blockIdx.x & 7;
    const int sg  = (blockIdx.x >> 3) & 7;
    const int h   = blockIdx.x >> 6;
    const int tid = threadIdx.x;
    const int s0  = sg * SEG + qt * 64;

    const float scale = 0.11180339887498948f;  // 1/sqrt(80)

    const float* Qg = g_q + (size_t)(h * S_LEN + s0) * HD;
    for (int l = tid; l < 64 * HD; l += 256) {
        int r = l / HD, d = l % HD;
        Qs[r * QS_STRIDE + d] = Qg[r * HD + d];
    }
    if (tid < 64) { rm[tid] = -1e30f; rl[tid] = 0.f; }

    const int row = tid >> 2;          // 0..63
    const int d0  = (tid & 3) * 20;    // 0,20,40,60
    float o[20];
#pragma unroll
    for (int i = 0; i < 20; ++i) o[i] = 0.f;
    __syncthreads();

    for (int kc = 0; kc < SEG / 64; ++kc) {
        const float* Kg = g_k + (size_t)(h * S_LEN + sg * SEG + kc * 64) * HD;
        const float* Vg = g_v + (size_t)(h * S_LEN + sg * SEG + kc * 64) * HD;
        for (int l = tid; l < 64 * HD; l += 256) {
            int r = l / HD, d = l % HD;
            Ks[r * KS_STRIDE + d] = Kg[r * HD + d];
            Vs[r * VS_STRIDE + d] = Vg[r * HD + d];
        }
        __syncthreads();

        {
            const int ti = (tid & 15) << 2;
            const int tj = (tid >> 4) << 2;
            float acc[4][4];
#pragma unroll
            for (int a = 0; a < 4; ++a)
#pragma unroll
                for (int b = 0; b < 4; ++b) acc[a][b] = 0.f;
#pragma unroll 8
            for (int k = 0; k < HD; ++k) {
                float qv[4], kv[4];
#pragma unroll
                for (int a = 0; a < 4; ++a) qv[a] = Qs[(ti + a) * QS_STRIDE + k];
#pragma unroll
                for (int b = 0; b < 4; ++b) kv[b] = Ks[(tj + b) * KS_STRIDE + k];
#pragma unroll
                for (int a = 0; a < 4; ++a)
#pragma unroll
                    for (int b = 0; b < 4; ++b)
                        acc[a][b] += qv[a] * kv[b];
            }
#pragma unroll
            for (int a = 0; a < 4; ++a)
#pragma unroll
                for (int b = 0; b < 4; ++b)
                    Sc[(ti + a) * SC_STRIDE + tj + b] = acc[a][b] * scale;
        }
        __syncthreads();

        if (tid < 64) {
            float mold = rm[tid];
            float mx = mold;
            float* srow = Sc + tid * SC_STRIDE;
#pragma unroll 8
            for (int j = 0; j < 64; ++j) mx = fmaxf(mx, srow[j]);
            float c  = __expf(mold - mx);
            float ls = 0.f;
#pragma unroll 8
            for (int j = 0; j < 64; ++j) {
                float p = __expf(srow[j] - mx);
                srow[j] = p;
                ls += p;
            }
            rl[tid] = rl[tid] * c + ls;
            rm[tid] = mx;
            rc[tid] = c;
        }
        __syncthreads();

        {
            float c = rc[row];
#pragma unroll
            for (int i = 0; i < 20; ++i) o[i] *= c;
            const float* srow = Sc + row * SC_STRIDE;
#pragma unroll 4
            for (int j = 0; j < 64; ++j) {
                float p = srow[j];
                const float4* v4 = (const float4*)&Vs[j * VS_STRIDE + d0];
#pragma unroll
                for (int q = 0; q < 5; ++q) {
                    float4 v = v4[q];
                    o[q * 4 + 0] += p * v.x;
                    o[q * 4 + 1] += p * v.y;
                    o[q * 4 + 2] += p * v.z;
                    o[q * 4 + 3] += p * v.w;
                }
            }
        }
        __syncthreads();
    }

    float inv = 1.f / rl[row];
    float* og = g_attn + (size_t)(s0 + row) * DIM + h * HD + d0;
#pragma unroll
    for (int i = 0; i < 20; ++i) og[i] = o[i] * inv;
}

// ---------------------------------------------------------------------------
extern "C" void kernel_launch(void* const* d_in, const int* in_sizes, int n_in,
                              void* d_out, int out_size)
{
    const float* hs     = (const float*)d_in[0];
    const float* cosb   = (const float*)d_in[1];
    const float* sinb   = (const float*)d_in[2];
    const float* qkv_w  = (const float*)d_in[3];
    const float* qkv_b  = (const float*)d_in[4];
    const float* proj_w = (const float*)d_in[5];
    const float* proj_b = (const float*)d_in[6];
    float* out = (float*)d_out;

    float *qkv_ptr, *attn_ptr;
    cudaGetSymbolAddress((void**)&qkv_ptr,  g_qkv);
    cudaGetSymbolAddress((void**)&attn_ptr, g_attn);

    cudaFuncSetAttribute(attn_kernel,
                         cudaFuncAttributeMaxDynamicSharedMemorySize, ATTN_SMEM);
    cudaFuncSetAttribute(gemm_bf16x3,
                         cudaFuncAttributeMaxDynamicSharedMemorySize, GSMEM_TOTAL);

    // 1) QKV GEMM: [4096,3840] = hs @ qkv_w^T + b
    {
        dim3 grid(3 * DIM / 128, S_LEN / 128);
        gemm_bf16x3<<<grid, 256, GSMEM_TOTAL>>>(hs, qkv_w, qkv_b, qkv_ptr,
                                                S_LEN, 3 * DIM, DIM);
    }
    // 2) RoPE + split into [H,S,D]
    {
        int total = S_LEN * NH * HD;
        rope_split<<<(total + 255) / 256, 256>>>(cosb, sinb);
    }
    // 3) Block-diagonal attention
    attn_kernel<<<NH * (S_LEN / SEG) * (SEG / 64), 256, ATTN_SMEM>>>();
    // 4) Proj GEMM: out = attn @ proj_w^T + b
    {
        dim3 grid(DIM / 128, S_LEN / 128);
        gemm_bf16x3<<<grid, 256, GSMEM_TOTAL>>>(attn_ptr, proj_w, proj_b, out,
                                                S_LEN, DIM, DIM);
    }
}